// round 2
// baseline (speedup 1.0000x reference)
#include <cuda_runtime.h>

// SpatialTransformer: 1-D bilinear warp along W (disparity shared across C).
//
// Strategy: one block per (b,h) row. Gather coefficients/indices are
// channel-invariant -> compute once per pixel, hold in registers.
// For each channel: stage the 512-float input row in smem via one
// LDG.128 + STS.128 per thread (depth-3 register prefetch pipeline),
// then gather via conflict-free LDS.32 (stride-128 thread->w mapping
// makes lanes hit consecutive smem words) and write coalesced STG.32.
// This cuts global-LSU warp-ops ~2.5x vs the direct-gather kernel,
// which was LSU-issue bound at 59.9% DRAM.

#define ST_B 4
#define ST_C 64
#define ST_H 256
#define ST_W 512

constexpr int THREADS = 128;
constexpr int WPT     = ST_W / THREADS;   // 4 pixels per thread

__global__ void __launch_bounds__(THREADS)
spatial_transformer_smem_kernel(const float* __restrict__ in,
                                const float* __restrict__ disp,
                                float* __restrict__ out)
{
    __shared__ float s_buf[2][ST_W];      // double-buffered channel row (4 KB)

    const int h = blockIdx.x;
    const int b = blockIdx.y;
    const int t = threadIdx.x;

    // ---- per-pixel coefficients, kept in registers (same mapping as gather) ----
    const float* drow = disp + (b * ST_H + h) * ST_W;

    float wa[WPT], wb[WPT];
    int   ia[WPT], ib[WPT];

    #pragma unroll
    for (int j = 0; j < WPT; ++j) {
        int   w  = t + j * THREADS;            // stride-128 mapping
        float ry = (float)w + __ldg(drow + w); // lanes -> consecutive w: coalesced
        float ra = floorf(ry);
        float fb = ry - ra;
        float fa = 1.0f - fb;
        int   a  = (int)ra;
        int   bb = a + 1;
        a  = min(max(a, 0), ST_W - 1);
        bb = min(max(bb, 0), ST_W - 1);
        float sc = (ry < 0.0f || ry > (float)(ST_W - 1)) ? 0.0f : 1.0f;
        wa[j] = fa * sc;
        wb[j] = fb * sc;
        ia[j] = a;
        ib[j] = bb;
    }

    const int chstride = ST_H * ST_W;
    const int base     = b * ST_C * chstride + h * ST_W;
    const float* src   = in  + base;
    float*       dst   = out + base;

    // ---- depth-3 register prefetch pipeline over channels ----
    float4 v0 = *(const float4*)(src + 0 * chstride + 4 * t);
    float4 v1 = *(const float4*)(src + 1 * chstride + 4 * t);
    float4 v2 = *(const float4*)(src + 2 * chstride + 4 * t);

    for (int c = 0; c < ST_C; ++c) {
        // stage channel c row into smem
        *(float4*)(&s_buf[c & 1][4 * t]) = v0;
        v0 = v1;
        v1 = v2;
        if (c + 3 < ST_C)
            v2 = *(const float4*)(src + (c + 3) * chstride + 4 * t);

        __syncthreads();   // STS visible to all; also WAR-protects buffer reuse

        const float* buf  = s_buf[c & 1];
        float*       orow = dst + c * chstride;

        #pragma unroll
        for (int j = 0; j < WPT; ++j) {
            int   w  = t + j * THREADS;
            float fa = buf[ia[j]];    // lanes -> consecutive ia: conflict-free
            float fb = buf[ib[j]];
            orow[w] = fmaf(wa[j], fa, wb[j] * fb);   // coalesced STG.32
        }
    }
}

extern "C" void kernel_launch(void* const* d_in, const int* in_sizes, int n_in,
                              void* d_out, int out_size)
{
    const float* right_input = (const float*)d_in[0];
    const float* disparity   = (const float*)d_in[1];
    float*       out         = (float*)d_out;

    dim3 grid(ST_H, ST_B);   // one block per (b,h) row: 1024 blocks
    spatial_transformer_smem_kernel<<<grid, THREADS>>>(right_input, disparity, out);
}